// round 1
// baseline (speedup 1.0000x reference)
#include <cuda_runtime.h>

#define TILE    32
#define HALO    5
#define KW      11
#define REGN    42        // TILE + 2*HALO
#define PITCH   43        // REGN + 1 (conflict-free for strided row access)
#define HPITCH  33        // TILE + 1
#define IMH     2048
#define IMW     2048
#define NCH     3
#define NTHREADS 256
#define NTILES  64

#define C1 1.0e-4f
#define C2 9.0e-4f

__device__ float g_partial[NTILES * NTILES];

__global__ __launch_bounds__(NTHREADS) void ssim_tile_kernel(
    const float* __restrict__ img1,
    const float* __restrict__ img2,
    const float* __restrict__ window)
{
    extern __shared__ float smem[];
    float* gtap = smem;                               // 16 floats (taps + pad)
    float* sx   = smem + 16;                          // NCH*REGN*PITCH
    float* sy   = sx + NCH * REGN * PITCH;            // NCH*REGN*PITCH
    float* hb   = sy + NCH * REGN * PITCH;            // 5*REGN*HPITCH

    const int tid = threadIdx.x;

    // Extract separable 1D taps from the 2D window: w2d = g g^T (exact).
    if (tid < KW) {
        float g5 = sqrtf(window[5 * KW + 5]);
        gtap[tid] = window[5 * KW + tid] / g5;
    }

    // ------- cooperative coalesced load: HWC interleaved -> planar smem -------
    const int row0 = (int)blockIdx.y * TILE - HALO;
    const int col0 = (int)blockIdx.x * TILE - HALO;
    const int ROWF = REGN * NCH;   // 126 contiguous floats per halo row
    for (int idx = tid; idx < REGN * ROWF; idx += NTHREADS) {
        int r = idx / ROWF;
        int f = idx - r * ROWF;
        int p = f / NCH;
        int c = f - p * NCH;
        int gr = row0 + r, gc = col0 + p;
        float v1 = 0.f, v2 = 0.f;
        if (gr >= 0 && gr < IMH && gc >= 0 && gc < IMW) {
            int off = (gr * IMW + gc) * NCH + c;
            v1 = img1[off];
            v2 = img2[off];
        }
        sx[(c * REGN + r) * PITCH + p] = v1;
        sy[(c * REGN + r) * PITCH + p] = v2;
    }
    __syncthreads();

    float lsum = 0.f;

    for (int c = 0; c < NCH; c++) {
        // ---------- horizontal pass: 4-wide register-blocked sliding window ----
        // work items: 42 rows x 8 groups of 4 output columns = 336
        for (int idx = tid; idx < REGN * 8; idx += NTHREADS) {
            int r  = idx >> 3;
            int j0 = (idx & 7) << 2;
            const float* px = &sx[(c * REGN + r) * PITCH + j0];
            const float* py = &sy[(c * REGN + r) * PITCH + j0];
            float a[4][5];
            #pragma unroll
            for (int o = 0; o < 4; o++)
                #pragma unroll
                for (int q = 0; q < 5; q++) a[o][q] = 0.f;

            #pragma unroll
            for (int t = 0; t < TILE/ TILE * 14; t++) {   // 14 = 4 + KW - 1
                float x = px[t], y = py[t];
                float xx = x * x, yy = y * y, xy = x * y;
                #pragma unroll
                for (int o = 0; o < 4; o++) {
                    int k = t - o;
                    if (k >= 0 && k < KW) {       // resolved at compile time
                        float w = gtap[k];
                        a[o][0] = fmaf(w, x,  a[o][0]);
                        a[o][1] = fmaf(w, y,  a[o][1]);
                        a[o][2] = fmaf(w, xx, a[o][2]);
                        a[o][3] = fmaf(w, yy, a[o][3]);
                        a[o][4] = fmaf(w, xy, a[o][4]);
                    }
                }
            }
            #pragma unroll
            for (int o = 0; o < 4; o++)
                #pragma unroll
                for (int q = 0; q < 5; q++)
                    hb[(q * REGN + r) * HPITCH + j0 + o] = a[o][q];
        }
        __syncthreads();

        // ---------- vertical pass: each thread produces 4 stacked outputs ------
        {
            int tx  = tid & 31;
            int ty0 = (tid >> 5) << 2;   // 8 warps * 4 rows = 32 rows
            float acc[4][5];
            #pragma unroll
            for (int o = 0; o < 4; o++)
                #pragma unroll
                for (int q = 0; q < 5; q++) acc[o][q] = 0.f;

            #pragma unroll
            for (int t = 0; t < 14; t++) {
                int r = ty0 + t;
                float h0 = hb[(0 * REGN + r) * HPITCH + tx];
                float h1 = hb[(1 * REGN + r) * HPITCH + tx];
                float h2 = hb[(2 * REGN + r) * HPITCH + tx];
                float h3 = hb[(3 * REGN + r) * HPITCH + tx];
                float h4 = hb[(4 * REGN + r) * HPITCH + tx];
                #pragma unroll
                for (int o = 0; o < 4; o++) {
                    int k = t - o;
                    if (k >= 0 && k < KW) {
                        float w = gtap[k];
                        acc[o][0] = fmaf(w, h0, acc[o][0]);
                        acc[o][1] = fmaf(w, h1, acc[o][1]);
                        acc[o][2] = fmaf(w, h2, acc[o][2]);
                        acc[o][3] = fmaf(w, h3, acc[o][3]);
                        acc[o][4] = fmaf(w, h4, acc[o][4]);
                    }
                }
            }
            #pragma unroll
            for (int o = 0; o < 4; o++) {
                float mu1 = acc[o][0], mu2 = acc[o][1];
                float mu12 = mu1 * mu2;
                float mu1s = mu1 * mu1, mu2s = mu2 * mu2;
                float s1  = acc[o][2] - mu1s;
                float s2  = acc[o][3] - mu2s;
                float s12 = acc[o][4] - mu12;
                float num = (2.f * mu12 + C1) * (2.f * s12 + C2);
                float den = (mu1s + mu2s + C1) * (s1 + s2 + C2);
                lsum += num / den;
            }
        }
        __syncthreads();  // hb is overwritten by next channel's horizontal pass
    }

    // ---------- block reduction of per-thread SSIM sums ----------
    #pragma unroll
    for (int s = 16; s > 0; s >>= 1)
        lsum += __shfl_xor_sync(0xffffffffu, lsum, s);
    __shared__ float red[8];
    if ((tid & 31) == 0) red[tid >> 5] = lsum;
    __syncthreads();
    if (tid == 0) {
        float bs = 0.f;
        #pragma unroll
        for (int i = 0; i < 8; i++) bs += red[i];
        g_partial[blockIdx.y * gridDim.x + blockIdx.x] = bs;
    }
}

__global__ void ssim_finalize(float* __restrict__ out)
{
    int tid = threadIdx.x;
    double s = 0.0;
    for (int i = tid; i < NTILES * NTILES; i += 256)
        s += (double)g_partial[i];
    #pragma unroll
    for (int sft = 16; sft > 0; sft >>= 1)
        s += __shfl_xor_sync(0xffffffffu, s, sft);
    __shared__ double rd[8];
    if ((tid & 31) == 0) rd[tid >> 5] = s;
    __syncthreads();
    if (tid == 0) {
        double t = 0.0;
        #pragma unroll
        for (int i = 0; i < 8; i++) t += rd[i];
        out[0] = (float)(1.0 - t / ((double)IMH * IMW * NCH));
    }
}

extern "C" void kernel_launch(void* const* d_in, const int* in_sizes, int n_in,
                              void* d_out, int out_size)
{
    const float* img1 = (const float*)d_in[0];
    const float* img2 = (const float*)d_in[1];
    const float* win  = (const float*)d_in[2];
    float* out = (float*)d_out;
    (void)in_sizes; (void)n_in; (void)out_size;

    const size_t SMEM = (size_t)(16 + 2 * NCH * REGN * PITCH + 5 * REGN * HPITCH)
                        * sizeof(float);   // 71128 bytes
    cudaFuncSetAttribute(ssim_tile_kernel,
                         cudaFuncAttributeMaxDynamicSharedMemorySize, (int)SMEM);

    dim3 grid(NTILES, NTILES);
    ssim_tile_kernel<<<grid, NTHREADS, SMEM>>>(img1, img2, win);
    ssim_finalize<<<1, 256>>>(out);
}

// round 2
// speedup vs baseline: 1.0486x; 1.0486x over previous
#include <cuda_runtime.h>

typedef unsigned long long ull;

#define TILE    32
#define HALO    5
#define KW      11
#define REGN    42          // TILE + 2*HALO rows in halo space
#define PP      43          // sxy pitch in float2 pairs
#define HP      33          // hb01/hb23 pitch in pairs
#define HP4     34          // hb4 pitch in floats
#define IMH     2048
#define IMW     2048
#define NCH     3
#define NTHREADS 256
#define NTILES  64

#define C1 1.0e-4f
#define C2 9.0e-4f

// smem layout (floats)
#define OFS_WWS   0                     // 12 shifted weight pairs = 24 floats
#define OFS_SXY   24                    // NCH*REGN*PP pairs = 10836 floats
#define OFS_H01   (OFS_SXY + NCH*REGN*PP*2)       // 10860
#define OFS_H23   (OFS_H01 + REGN*HP*2)           // +2772
#define OFS_H4    (OFS_H23 + REGN*HP*2)           // +2772
#define SMEM_FLOATS (OFS_H4 + REGN*HP4)           // +1428 => 17832

__device__ float g_partial[NTILES * NTILES];
__device__ unsigned int g_flag;   // zero-init; last block resets it

__device__ __forceinline__ ull pack2(float lo, float hi) {
    ull r; asm("mov.b64 %0,{%1,%2};" : "=l"(r) : "f"(lo), "f"(hi)); return r;
}
__device__ __forceinline__ float2 unpack2(ull v) {
    float2 r; asm("mov.b64 {%0,%1},%2;" : "=f"(r.x), "=f"(r.y) : "l"(v)); return r;
}
__device__ __forceinline__ ull fma2(ull a, ull b, ull c) {
    ull d; asm("fma.rn.f32x2 %0,%1,%2,%3;" : "=l"(d) : "l"(a), "l"(b), "l"(c)); return d;
}
__device__ __forceinline__ ull mul2(ull a, ull b) {
    ull d; asm("mul.rn.f32x2 %0,%1,%2;" : "=l"(d) : "l"(a), "l"(b)); return d;
}

__global__ __launch_bounds__(NTHREADS) void ssim_tile_kernel(
    const float* __restrict__ img1,
    const float* __restrict__ img2,
    const float* __restrict__ window,
    float* __restrict__ out)
{
    extern __shared__ float smem[];
    ull*   wwsP = (ull*)(smem + OFS_WWS);        // (w[k], w[k-1]) pairs, k=0..11
    float* sxyF = smem + OFS_SXY;                // interleaved (x,y) pairs
    float* h01F = smem + OFS_H01;                // (mu1h, mu2h) pairs
    float* h23F = smem + OFS_H23;                // (xxh, yyh) pairs
    float* h4F  = smem + OFS_H4;                 // xyh scalars

    const int tid = threadIdx.x;

    // ---- separable taps: w2d = g g^T exactly, so g_k = w2d[5][k] / sqrt(w2d[5][5])
    float wt[KW];
    {
        float g5 = sqrtf(window[5 * KW + 5]);
        #pragma unroll
        for (int k = 0; k < KW; k++) wt[k] = window[5 * KW + k] / g5;
    }
    ull wwr[KW];                                  // (w,w) broadcast pairs in regs
    #pragma unroll
    for (int k = 0; k < KW; k++) wwr[k] = pack2(wt[k], wt[k]);
    if (tid < 12) {
        float lo = (tid < KW)      ? wt[tid]     : 0.f;
        float hi = (tid >= 1)      ? wt[tid - 1] : 0.f;
        wwsP[tid] = pack2(lo, hi);                // shifted pair for packed xy accum
    }

    // ---- cooperative coalesced load: HWC interleaved -> planar (x,y) pairs ----
    const int row0 = (int)blockIdx.y * TILE - HALO;
    const int col0 = (int)blockIdx.x * TILE - HALO;
    const int ROWF = REGN * NCH;                  // 126 contiguous floats / halo row
    for (int idx = tid; idx < REGN * ROWF; idx += NTHREADS) {
        int r = idx / ROWF;
        int f = idx - r * ROWF;
        int p = f / NCH;
        int c = f - p * NCH;
        int gr = row0 + r, gc = col0 + p;
        float v1 = 0.f, v2 = 0.f;
        if (gr >= 0 && gr < IMH && gc >= 0 && gc < IMW) {
            int off = (gr * IMW + gc) * NCH + c;
            v1 = img1[off];
            v2 = img2[off];
        }
        ((float2*)sxyF)[(c * REGN + r) * PP + p] = make_float2(v1, v2);
    }
    __syncthreads();

    float lsum = 0.f;

    for (int c = 0; c < NCH; c++) {
        // ---------- horizontal pass: 4-wide register-blocked, f32x2 packed -----
        // 336 items: lane -> row (42), group -> 4 output pairs; 43r mod 16 cycles
        for (int idx = tid; idx < REGN * 8; idx += NTHREADS) {
            int r  = idx % REGN;
            int g  = idx / REGN;
            int j0 = g << 2;
            const ull* pxy = (const ull*)sxyF + (c * REGN + r) * PP + j0;

            ull axy[4], ass[4], ap2[2];
            #pragma unroll
            for (int o = 0; o < 4; o++) { axy[o] = 0; ass[o] = 0; }
            ap2[0] = 0; ap2[1] = 0;

            #pragma unroll
            for (int t = 0; t < 14; t++) {
                ull vxy = pxy[t];
                ull vss = mul2(vxy, vxy);
                float2 fv = unpack2(vxy);
                float xy = fv.x * fv.y;
                ull pxy2 = pack2(xy, xy);
                #pragma unroll
                for (int o = 0; o < 4; o++) {
                    int k = t - o;
                    if (k >= 0 && k < KW) {          // compile-time resolved
                        axy[o] = fma2(wwr[k], vxy, axy[o]);
                        ass[o] = fma2(wwr[k], vss, ass[o]);
                    }
                }
                #pragma unroll
                for (int p = 0; p < 2; p++) {
                    int k = t - 2 * p;               // pair covers outputs 2p,2p+1
                    if (k >= 0 && k < 12) {
                        ap2[p] = fma2(wwsP[k], pxy2, ap2[p]);
                    }
                }
            }
            ull* d01 = (ull*)h01F + r * HP + j0;
            ull* d23 = (ull*)h23F + r * HP + j0;
            #pragma unroll
            for (int o = 0; o < 4; o++) { d01[o] = axy[o]; d23[o] = ass[o]; }
            ull* d4 = (ull*)(h4F + r * HP4) + (j0 >> 1);
            d4[0] = ap2[0];
            d4[1] = ap2[1];
        }
        __syncthreads();

        // ---------- vertical pass: 4 stacked outputs / thread, f32x2 packed ----
        {
            int tx  = tid & 31;
            int ty0 = (tid >> 5) << 2;
            ull a01[4], a23[4], ap2[2];
            #pragma unroll
            for (int o = 0; o < 4; o++) { a01[o] = 0; a23[o] = 0; }
            ap2[0] = 0; ap2[1] = 0;

            #pragma unroll
            for (int t = 0; t < 14; t++) {
                int r = ty0 + t;
                ull h01 = ((const ull*)h01F)[r * HP + tx];
                ull h23 = ((const ull*)h23F)[r * HP + tx];
                float h4 = h4F[r * HP4 + tx];
                ull ph4 = pack2(h4, h4);
                #pragma unroll
                for (int o = 0; o < 4; o++) {
                    int k = t - o;
                    if (k >= 0 && k < KW) {
                        a01[o] = fma2(wwr[k], h01, a01[o]);
                        a23[o] = fma2(wwr[k], h23, a23[o]);
                    }
                }
                #pragma unroll
                for (int p = 0; p < 2; p++) {
                    int k = t - 2 * p;
                    if (k >= 0 && k < 12) {
                        ap2[p] = fma2(wwsP[k], ph4, ap2[p]);
                    }
                }
            }
            float2 e0 = unpack2(ap2[0]);
            float2 e1 = unpack2(ap2[1]);
            float exy[4] = {e0.x, e0.y, e1.x, e1.y};
            #pragma unroll
            for (int o = 0; o < 4; o++) {
                float2 mu = unpack2(a01[o]);
                float2 ss = unpack2(a23[o]);
                float mu12 = mu.x * mu.y;
                float mu1s = mu.x * mu.x, mu2s = mu.y * mu.y;
                float s1  = ss.x   - mu1s;
                float s2  = ss.y   - mu2s;
                float s12 = exy[o] - mu12;
                float num = (2.f * mu12 + C1) * (2.f * s12 + C2);
                float den = (mu1s + mu2s + C1) * (s1 + s2 + C2);
                lsum += __fdividef(num, den);
            }
        }
        __syncthreads();   // hb reused next channel
    }

    // ---------- block reduction ----------
    #pragma unroll
    for (int s = 16; s > 0; s >>= 1)
        lsum += __shfl_xor_sync(0xffffffffu, lsum, s);
    __shared__ float red[8];
    if ((tid & 31) == 0) red[tid >> 5] = lsum;
    __syncthreads();
    if (tid == 0) {
        float bs = 0.f;
        #pragma unroll
        for (int i = 0; i < 8; i++) bs += red[i];
        g_partial[blockIdx.y * gridDim.x + blockIdx.x] = bs;
    }

    // ---------- last-block finalize (no second launch) ----------
    __shared__ bool amLast;
    __threadfence();
    if (tid == 0) {
        unsigned int n = atomicAdd(&g_flag, 1u);
        amLast = (n == (unsigned)(NTILES * NTILES - 1));
    }
    __syncthreads();
    if (amLast) {
        double s = 0.0;
        for (int i = tid; i < NTILES * NTILES; i += NTHREADS)
            s += (double)g_partial[i];
        #pragma unroll
        for (int sft = 16; sft > 0; sft >>= 1)
            s += __shfl_xor_sync(0xffffffffu, s, sft);
        __shared__ double rd[8];
        if ((tid & 31) == 0) rd[tid >> 5] = s;
        __syncthreads();
        if (tid == 0) {
            double t = 0.0;
            #pragma unroll
            for (int i = 0; i < 8; i++) t += rd[i];
            out[0] = (float)(1.0 - t / ((double)IMH * IMW * NCH));
            g_flag = 0;                 // reset for next graph replay
        }
    }
}

extern "C" void kernel_launch(void* const* d_in, const int* in_sizes, int n_in,
                              void* d_out, int out_size)
{
    const float* img1 = (const float*)d_in[0];
    const float* img2 = (const float*)d_in[1];
    const float* win  = (const float*)d_in[2];
    float* out = (float*)d_out;
    (void)in_sizes; (void)n_in; (void)out_size;

    const size_t SMEM = (size_t)SMEM_FLOATS * sizeof(float);   // 71328 B
    cudaFuncSetAttribute(ssim_tile_kernel,
                         cudaFuncAttributeMaxDynamicSharedMemorySize, (int)SMEM);

    dim3 grid(NTILES, NTILES);
    ssim_tile_kernel<<<grid, NTHREADS, SMEM>>>(img1, img2, win, out);
}

// round 3
// speedup vs baseline: 1.1578x; 1.1042x over previous
#include <cuda_runtime.h>

typedef unsigned long long ull;

#define TILE    32
#define HALO    5
#define KW      11
#define REGN    42          // TILE + 2*HALO rows/cols in halo space
#define PP      43          // sxy pitch in (u,v) pairs
#define HP      33          // h-buffer pitch in float4
#define IMH     2048
#define IMW     2048
#define NCH     3
#define NTHREADS 256
#define NTILES  64

#define C1 1.0e-4f
#define C2 9.0e-4f

// smem layout (floats)
#define OFS_SXY   0                                // NCH*REGN*PP pairs
#define OFS_H     (NCH*REGN*PP*2)                  // 10836
#define SMEM_FLOATS (OFS_H + REGN*HP*4)            // +5544 = 16380 (65520 B)

__device__ float g_partial[NTILES * NTILES];
__device__ unsigned int g_flag;   // zero-init; last block resets it

__device__ __forceinline__ ull pack2(float lo, float hi) {
    ull r; asm("mov.b64 %0,{%1,%2};" : "=l"(r) : "f"(lo), "f"(hi)); return r;
}
__device__ __forceinline__ float2 unpack2(ull v) {
    float2 r; asm("mov.b64 {%0,%1},%2;" : "=f"(r.x), "=f"(r.y) : "l"(v)); return r;
}
__device__ __forceinline__ ull fma2(ull a, ull b, ull c) {
    ull d; asm("fma.rn.f32x2 %0,%1,%2,%3;" : "=l"(d) : "l"(a), "l"(b), "l"(c)); return d;
}
__device__ __forceinline__ ull mul2(ull a, ull b) {
    ull d; asm("mul.rn.f32x2 %0,%1,%2;" : "=l"(d) : "l"(a), "l"(b)); return d;
}

__global__ __launch_bounds__(NTHREADS) void ssim_tile_kernel(
    const float* __restrict__ img1,
    const float* __restrict__ img2,
    const float* __restrict__ window,
    float* __restrict__ out)
{
    extern __shared__ float smem[];
    float* sxyF = smem + OFS_SXY;                // interleaved (u,v) pairs
    float* hF   = smem + OFS_H;                  // (U,V,Su,Sv) float4 per column

    const int tid = threadIdx.x;

    // ---- separable taps: w2d = g g^T exactly, so g_k = w2d[5][k] / sqrt(w2d[5][5])
    ull wwr[KW];                                  // (w,w) broadcast pairs in regs
    {
        float g5 = sqrtf(window[5 * KW + 5]);
        #pragma unroll
        for (int k = 0; k < KW; k++) {
            float w = window[5 * KW + k] / g5;
            wwr[k] = pack2(w, w);
        }
    }

    // ---- cooperative coalesced load: HWC interleaved -> planar (u,v) pairs ----
    const int row0 = (int)blockIdx.y * TILE - HALO;
    const int col0 = (int)blockIdx.x * TILE - HALO;
    const int ROWF = REGN * NCH;                  // 126 contiguous floats / halo row
    for (int idx = tid; idx < REGN * ROWF; idx += NTHREADS) {
        int r = idx / ROWF;
        int f = idx - r * ROWF;
        int p = f / NCH;
        int c = f - p * NCH;
        int gr = row0 + r, gc = col0 + p;
        float v1 = 0.f, v2 = 0.f;
        if (gr >= 0 && gr < IMH && gc >= 0 && gc < IMW) {
            int off = (gr * IMW + gc) * NCH + c;
            v1 = img1[off];
            v2 = img2[off];
        }
        // zero padding commutes with the linear transform (u,v)=(x+y, x-y)
        ((float2*)sxyF)[(c * REGN + r) * PP + p] = make_float2(v1 + v2, v1 - v2);
    }
    __syncthreads();

    float lsum = 0.f;

    for (int c = 0; c < NCH; c++) {
        // ---------- horizontal pass: 4-wide register-blocked, fully packed -----
        for (int idx = tid; idx < REGN * 8; idx += NTHREADS) {
            int r  = idx % REGN;
            int j0 = (idx / REGN) << 2;
            const ull* puv = (const ull*)sxyF + (c * REGN + r) * PP + j0;

            ull auv[4], ass[4];
            #pragma unroll
            for (int o = 0; o < 4; o++) { auv[o] = 0; ass[o] = 0; }

            #pragma unroll
            for (int t = 0; t < 14; t++) {
                ull vuv = puv[t];
                ull vss = mul2(vuv, vuv);
                #pragma unroll
                for (int o = 0; o < 4; o++) {
                    int k = t - o;
                    if (k >= 0 && k < KW) {          // compile-time resolved
                        auv[o] = fma2(wwr[k], vuv, auv[o]);
                        ass[o] = fma2(wwr[k], vss, ass[o]);
                    }
                }
            }
            float4* dst = (float4*)hF + r * HP + j0;
            #pragma unroll
            for (int o = 0; o < 4; o++) {
                float2 a = unpack2(auv[o]);
                float2 b = unpack2(ass[o]);
                dst[o] = make_float4(a.x, a.y, b.x, b.y);
            }
        }
        __syncthreads();

        // ---------- vertical pass: 4 stacked outputs / thread, packed ----------
        {
            int tx  = tid & 31;
            int ty0 = (tid >> 5) << 2;
            ull aU[4], aS[4];
            #pragma unroll
            for (int o = 0; o < 4; o++) { aU[o] = 0; aS[o] = 0; }

            #pragma unroll
            for (int t = 0; t < 14; t++) {
                int r = ty0 + t;
                float4 h = ((const float4*)hF)[r * HP + tx];
                ull huv = pack2(h.x, h.y);
                ull hss = pack2(h.z, h.w);
                #pragma unroll
                for (int o = 0; o < 4; o++) {
                    int k = t - o;
                    if (k >= 0 && k < KW) {
                        aU[o] = fma2(wwr[k], huv, aU[o]);
                        aS[o] = fma2(wwr[k], hss, aS[o]);
                    }
                }
            }
            #pragma unroll
            for (int o = 0; o < 4; o++) {
                float2 uv = unpack2(aU[o]);      // U = mu1+mu2, V = mu1-mu2
                float2 ss = unpack2(aS[o]);      // Su = E[u^2], Sv = E[v^2]
                float U2 = uv.x * uv.x;
                float V2 = uv.y * uv.y;
                float A  = ss.x - U2;            // = s1+s2+2*s12 (x2 scale)
                float B  = ss.y - V2;            // = s1+s2-2*s12 (x2 scale)
                float num = fmaf(0.5f, U2 - V2, C1) * fmaf(0.5f, A - B, C2);
                float den = fmaf(0.5f, U2 + V2, C1) * fmaf(0.5f, A + B, C2);
                lsum += __fdividef(num, den);
            }
        }
        __syncthreads();   // h buffer reused next channel
    }

    // ---------- block reduction ----------
    #pragma unroll
    for (int s = 16; s > 0; s >>= 1)
        lsum += __shfl_xor_sync(0xffffffffu, lsum, s);
    __shared__ float red[8];
    if ((tid & 31) == 0) red[tid >> 5] = lsum;
    __syncthreads();
    if (tid == 0) {
        float bs = 0.f;
        #pragma unroll
        for (int i = 0; i < 8; i++) bs += red[i];
        g_partial[blockIdx.y * gridDim.x + blockIdx.x] = bs;
    }

    // ---------- last-block finalize (no second launch) ----------
    __shared__ bool amLast;
    __threadfence();
    if (tid == 0) {
        unsigned int n = atomicAdd(&g_flag, 1u);
        amLast = (n == (unsigned)(NTILES * NTILES - 1));
    }
    __syncthreads();
    if (amLast) {
        double s = 0.0;
        for (int i = tid; i < NTILES * NTILES; i += NTHREADS)
            s += (double)g_partial[i];
        #pragma unroll
        for (int sft = 16; sft > 0; sft >>= 1)
            s += __shfl_xor_sync(0xffffffffu, s, sft);
        __shared__ double rd[8];
        if ((tid & 31) == 0) rd[tid >> 5] = s;
        __syncthreads();
        if (tid == 0) {
            double t = 0.0;
            #pragma unroll
            for (int i = 0; i < 8; i++) t += rd[i];
            out[0] = (float)(1.0 - t / ((double)IMH * IMW * NCH));
            g_flag = 0;                 // reset for next graph replay
        }
    }
}

extern "C" void kernel_launch(void* const* d_in, const int* in_sizes, int n_in,
                              void* d_out, int out_size)
{
    const float* img1 = (const float*)d_in[0];
    const float* img2 = (const float*)d_in[1];
    const float* win  = (const float*)d_in[2];
    float* out = (float*)d_out;
    (void)in_sizes; (void)n_in; (void)out_size;

    const size_t SMEM = (size_t)SMEM_FLOATS * sizeof(float);   // 65520 B
    cudaFuncSetAttribute(ssim_tile_kernel,
                         cudaFuncAttributeMaxDynamicSharedMemorySize, (int)SMEM);

    dim3 grid(NTILES, NTILES);
    ssim_tile_kernel<<<grid, NTHREADS, SMEM>>>(img1, img2, win, out);
}

// round 4
// speedup vs baseline: 1.2464x; 1.0766x over previous
#include <cuda_runtime.h>

typedef unsigned long long ull;

#define TILE    32
#define HALO    5
#define KW      11
#define REGN    42          // TILE + 2*HALO
#define PP      43          // sxy pitch in (u,v) pairs (ull)
#define HP      33          // h-buffer pitch in float4
#define IMH     2048
#define IMW     2048
#define NCH     3
#define NTHREADS 256
#define NTILES  64

#define C1 1.0e-4f
#define C2 9.0e-4f

// per-channel smem layout (floats)
#define OFS_SXY  0                              // REGN*PP ull = 3612 floats
#define OFS_H    (REGN*PP*2)                    // 3612
#define SMEM_FLOATS (OFS_H + REGN*HP*4)         // +5544 = 9156 (36624 B)

__device__ float g_partial[NTILES * NTILES];
__device__ unsigned int g_flag;   // zero-init; last block resets it

__device__ __forceinline__ ull pack2(float lo, float hi) {
    ull r; asm("mov.b64 %0,{%1,%2};" : "=l"(r) : "f"(lo), "f"(hi)); return r;
}
__device__ __forceinline__ float2 unpack2(ull v) {
    float2 r; asm("mov.b64 {%0,%1},%2;" : "=f"(r.x), "=f"(r.y) : "l"(v)); return r;
}
__device__ __forceinline__ ull fma2(ull a, ull b, ull c) {
    ull d; asm("fma.rn.f32x2 %0,%1,%2,%3;" : "=l"(d) : "l"(a), "l"(b), "l"(c)); return d;
}
__device__ __forceinline__ ull mul2(ull a, ull b) {
    ull d; asm("mul.rn.f32x2 %0,%1,%2;" : "=l"(d) : "l"(a), "l"(b)); return d;
}

__global__ __launch_bounds__(NTHREADS, 6) void ssim_tile_kernel(
    const float* __restrict__ img1,
    const float* __restrict__ img2,
    const float* __restrict__ window,
    float* __restrict__ out)
{
    extern __shared__ float smem[];
    float* sxyF = smem + OFS_SXY;                // (u,v) pairs, one channel
    float* hF   = smem + OFS_H;                  // (U,V,Su,Sv) float4 per column

    const int tid = threadIdx.x;

    // ---- separable taps: w2d = g g^T exactly, so g_k = w2d[5][k] / sqrt(w2d[5][5])
    ull wwr[KW];                                  // (w,w) broadcast pairs in regs
    {
        float g5 = sqrtf(window[5 * KW + 5]);
        #pragma unroll
        for (int k = 0; k < KW; k++) {
            float w = window[5 * KW + k] / g5;
            wwr[k] = pack2(w, w);
        }
    }

    const int row0 = (int)blockIdx.y * TILE - HALO;
    const int col0 = (int)blockIdx.x * TILE - HALO;

    float lsum = 0.f;

    for (int c = 0; c < NCH; c++) {
        // ---------- per-channel load: HWC global -> (u,v) pairs in smem -------
        for (int idx = tid; idx < REGN * REGN; idx += NTHREADS) {
            int r = idx / REGN;
            int p = idx - r * REGN;
            int gr = row0 + r, gc = col0 + p;
            float v1 = 0.f, v2 = 0.f;
            if (gr >= 0 && gr < IMH && gc >= 0 && gc < IMW) {
                int off = (gr * IMW + gc) * NCH + c;
                v1 = img1[off];
                v2 = img2[off];
            }
            // zero padding commutes with (u,v) = (x+y, x-y)
            ((float2*)sxyF)[r * PP + p] = make_float2(v1 + v2, v1 - v2);
        }
        __syncthreads();

        // ---------- horizontal pass: 4-wide register-blocked, fully packed ----
        for (int idx = tid; idx < REGN * 8; idx += NTHREADS) {
            int r  = idx % REGN;
            int j0 = (idx / REGN) << 2;
            const ull* puv = (const ull*)sxyF + r * PP + j0;

            ull auv[4], ass[4];
            #pragma unroll
            for (int o = 0; o < 4; o++) { auv[o] = 0; ass[o] = 0; }

            #pragma unroll
            for (int t = 0; t < 14; t++) {
                ull vuv = puv[t];
                ull vss = mul2(vuv, vuv);
                #pragma unroll
                for (int o = 0; o < 4; o++) {
                    int k = t - o;
                    if (k >= 0 && k < KW) {          // compile-time resolved
                        auv[o] = fma2(wwr[k], vuv, auv[o]);
                        ass[o] = fma2(wwr[k], vss, ass[o]);
                    }
                }
            }
            float4* dst = (float4*)hF + r * HP + j0;
            #pragma unroll
            for (int o = 0; o < 4; o++) {
                float2 a = unpack2(auv[o]);
                float2 b = unpack2(ass[o]);
                dst[o] = make_float4(a.x, a.y, b.x, b.y);
            }
        }
        __syncthreads();   // protects sxy (read done) and h (writes visible)

        // ---------- vertical pass: 4 stacked outputs / thread, packed ---------
        {
            int tx  = tid & 31;
            int ty0 = (tid >> 5) << 2;
            ull aU[4], aS[4];
            #pragma unroll
            for (int o = 0; o < 4; o++) { aU[o] = 0; aS[o] = 0; }

            #pragma unroll
            for (int t = 0; t < 14; t++) {
                int r = ty0 + t;
                float4 h = ((const float4*)hF)[r * HP + tx];
                ull huv = pack2(h.x, h.y);
                ull hss = pack2(h.z, h.w);
                #pragma unroll
                for (int o = 0; o < 4; o++) {
                    int k = t - o;
                    if (k >= 0 && k < KW) {
                        aU[o] = fma2(wwr[k], huv, aU[o]);
                        aS[o] = fma2(wwr[k], hss, aS[o]);
                    }
                }
            }
            #pragma unroll
            for (int o = 0; o < 4; o++) {
                float2 uv = unpack2(aU[o]);      // U = mu1+mu2, V = mu1-mu2
                float2 ss = unpack2(aS[o]);      // Su = E[u^2], Sv = E[v^2]
                float U2 = uv.x * uv.x;
                float V2 = uv.y * uv.y;
                float A  = ss.x - U2;            // = s1+s2+2*s12 (x2 scale)
                float B  = ss.y - V2;            // = s1+s2-2*s12 (x2 scale)
                float num = fmaf(0.5f, U2 - V2, C1) * fmaf(0.5f, A - B, C2);
                float den = fmaf(0.5f, U2 + V2, C1) * fmaf(0.5f, A + B, C2);
                lsum += __fdividef(num, den);
            }
        }
        // next channel's load (after its own implicit position in loop) is
        // separated from vertical reads of h by the post-load __syncthreads()
        __syncthreads();
    }

    // ---------- block reduction ----------
    #pragma unroll
    for (int s = 16; s > 0; s >>= 1)
        lsum += __shfl_xor_sync(0xffffffffu, lsum, s);
    __shared__ float red[8];
    if ((tid & 31) == 0) red[tid >> 5] = lsum;
    __syncthreads();
    if (tid == 0) {
        float bs = 0.f;
        #pragma unroll
        for (int i = 0; i < 8; i++) bs += red[i];
        g_partial[blockIdx.y * gridDim.x + blockIdx.x] = bs;
    }

    // ---------- last-block finalize (no second launch) ----------
    __shared__ bool amLast;
    __threadfence();
    if (tid == 0) {
        unsigned int n = atomicAdd(&g_flag, 1u);
        amLast = (n == (unsigned)(NTILES * NTILES - 1));
    }
    __syncthreads();
    if (amLast) {
        double s = 0.0;
        for (int i = tid; i < NTILES * NTILES; i += NTHREADS)
            s += (double)g_partial[i];
        #pragma unroll
        for (int sft = 16; sft > 0; sft >>= 1)
            s += __shfl_xor_sync(0xffffffffu, s, sft);
        __shared__ double rd[8];
        if ((tid & 31) == 0) rd[tid >> 5] = s;
        __syncthreads();
        if (tid == 0) {
            double t = 0.0;
            #pragma unroll
            for (int i = 0; i < 8; i++) t += rd[i];
            out[0] = (float)(1.0 - t / ((double)IMH * IMW * NCH));
            g_flag = 0;                 // reset for next graph replay
        }
    }
}

extern "C" void kernel_launch(void* const* d_in, const int* in_sizes, int n_in,
                              void* d_out, int out_size)
{
    const float* img1 = (const float*)d_in[0];
    const float* img2 = (const float*)d_in[1];
    const float* win  = (const float*)d_in[2];
    float* out = (float*)d_out;
    (void)in_sizes; (void)n_in; (void)out_size;

    const size_t SMEM = (size_t)SMEM_FLOATS * sizeof(float);   // 36624 B
    cudaFuncSetAttribute(ssim_tile_kernel,
                         cudaFuncAttributeMaxDynamicSharedMemorySize, (int)SMEM);

    dim3 grid(NTILES, NTILES);
    ssim_tile_kernel<<<grid, NTHREADS, SMEM>>>(img1, img2, win, out);
}